// round 1
// baseline (speedup 1.0000x reference)
#include <cuda_runtime.h>
#include <math.h>

// Problem constants
#define B_      8192
#define IN_     512
#define CTX_    256
#define CENTER_ 512
#define FF_     1024
#define RNN_    1024
#define OUT_    512
#define O2C_    256
#define TOT_    768   // OUT_ + O2C_

// Scratch (allocation-free rule: __device__ globals)
__device__ float g_scale;                       // 1/max(||W_read||_F, 1)
__device__ float g_wfused[CENTER_ * FF_];       // scale * (W_read @ W_pre[512:768,:])
__device__ float g_rnn[(size_t)B_ * FF_];       // rnn_in = relu(...)

// ---------------------------------------------------------------------------
// Norm reduction: scale = 1 / max(||W_read||_F, 1)
// ---------------------------------------------------------------------------
__global__ void norm_kernel(const float* __restrict__ W) {
    __shared__ double red[256];
    double s = 0.0;
    for (int i = threadIdx.x; i < CENTER_ * CTX_; i += 256) {
        float v = W[i];
        s += (double)v * (double)v;
    }
    red[threadIdx.x] = s;
    __syncthreads();
    for (int o = 128; o > 0; o >>= 1) {
        if (threadIdx.x < o) red[threadIdx.x] += red[threadIdx.x + o];
        __syncthreads();
    }
    if (threadIdx.x == 0) {
        float n = (float)sqrt(red[0]);
        g_scale = 1.0f / fmaxf(n, 1.0f);
    }
}

// ---------------------------------------------------------------------------
// Generic dual-segment SGEMM: C = epi( A0@B0 + A1@B1 + bias )
//   A row-major [M, K] with leading dim lda; B row-major [K, N] with ld = N.
//   All M multiples of 128, N multiples of 128, K multiples of 16.
// Tiling: 128x128 block tile, BK=16, 256 threads, 8x8 per-thread micro-tile.
// ---------------------------------------------------------------------------
#define BM 128
#define BN 128
#define BK 16

#define EPI_SCALE      0
#define EPI_RELU       1
#define EPI_TANH       2
#define EPI_RELU_SPLIT 3

template <int EPI>
__global__ __launch_bounds__(256, 2)
void gemm_dual(const float* __restrict__ A0, int lda0,
               const float* __restrict__ B0, int K0,
               const float* __restrict__ A1, int lda1,
               const float* __restrict__ B1, int K1,
               const float* __restrict__ bias,
               float* __restrict__ C0, float* __restrict__ C1,
               int N, int splitN)
{
    __shared__ float As[BK][BM + 4];   // +4 pad: reduce STS bank conflicts
    __shared__ float Bs[BK][BN];

    const int tid = threadIdx.x;
    const int tx = tid & 15;           // 0..15  -> 8 output cols each
    const int ty = tid >> 4;           // 0..15  -> 8 output rows each
    const int rowBase = blockIdx.y * BM;
    const int colBase = blockIdx.x * BN;

    float acc[8][8];
#pragma unroll
    for (int m = 0; m < 8; m++)
#pragma unroll
        for (int n = 0; n < 8; n++) acc[m][n] = 0.0f;

    // A tile: 128x16 = 512 float4; 2 per thread. f = tid, tid+256.
    const int a_row0 = tid >> 2;       // 0..63
    const int a_c4   = tid & 3;        // float4 column within 16
    // B tile: 16x128 = 512 float4; 2 per thread.
    const int b_k0   = tid >> 5;       // 0..7
    const int b_c4   = tid & 31;       // float4 column within 128

#pragma unroll 1
    for (int seg = 0; seg < 2; seg++) {
        const float* A  = seg ? A1 : A0;
        const float* Bm = seg ? B1 : B0;
        const int lda   = seg ? lda1 : lda0;
        const int K     = seg ? K1 : K0;

        for (int kb = 0; kb < K; kb += BK) {
            // Load A tile, transposed into As[k][row]
#pragma unroll
            for (int h = 0; h < 2; h++) {
                int r = a_row0 + h * 64;
                const float4 v = *(const float4*)(A + (size_t)(rowBase + r) * lda
                                                   + kb + a_c4 * 4);
                As[a_c4 * 4 + 0][r] = v.x;
                As[a_c4 * 4 + 1][r] = v.y;
                As[a_c4 * 4 + 2][r] = v.z;
                As[a_c4 * 4 + 3][r] = v.w;
            }
            // Load B tile
#pragma unroll
            for (int h = 0; h < 2; h++) {
                int kr = b_k0 + h * 8;
                const float4 v = *(const float4*)(Bm + (size_t)(kb + kr) * N
                                                   + colBase + b_c4 * 4);
                *(float4*)&Bs[kr][b_c4 * 4] = v;
            }
            __syncthreads();

#pragma unroll
            for (int k = 0; k < BK; k++) {
                float a[8], b[8];
#pragma unroll
                for (int m = 0; m < 8; m++) a[m] = As[k][ty * 8 + m];
#pragma unroll
                for (int n = 0; n < 8; n++) b[n] = Bs[k][tx * 8 + n];
#pragma unroll
                for (int m = 0; m < 8; m++)
#pragma unroll
                    for (int n = 0; n < 8; n++)
                        acc[m][n] = fmaf(a[m], b[n], acc[m][n]);
            }
            __syncthreads();
        }
    }

    // Epilogue
    const float scale = (EPI == EPI_SCALE) ? g_scale : 0.0f;
#pragma unroll
    for (int m = 0; m < 8; m++) {
        const int row = rowBase + ty * 8 + m;
#pragma unroll
        for (int n = 0; n < 8; n++) {
            const int col = colBase + tx * 8 + n;
            float v = acc[m][n];
            if (EPI == EPI_SCALE) {
                C0[(size_t)row * N + col] = v * scale;
            } else {
                v += bias[col];
                if (EPI == EPI_RELU) {
                    C0[(size_t)row * N + col] = fmaxf(v, 0.0f);
                } else if (EPI == EPI_TANH) {
                    C0[(size_t)row * N + col] = tanhf(v);
                } else { // EPI_RELU_SPLIT
                    v = fmaxf(v, 0.0f);
                    if (col < splitN)
                        C0[(size_t)row * splitN + col] = v;
                    else
                        C1[(size_t)row * (N - splitN) + (col - splitN)] = v;
                }
            }
        }
    }
}

// ---------------------------------------------------------------------------
// Launch
// ---------------------------------------------------------------------------
extern "C" void kernel_launch(void* const* d_in, const int* in_sizes, int n_in,
                              void* d_out, int out_size)
{
    const float* inputs = (const float*)d_in[0];   // (B,1,512)
    const float* center = (const float*)d_in[1];   // (B,1,512)
    const float* mstate = (const float*)d_in[2];   // (B,1,1024)
    const float* W_read = (const float*)d_in[3];   // (512,256)
    const float* W_pre  = (const float*)d_in[4];   // (768,1024)
    const float* b_pre  = (const float*)d_in[5];   // (1024)
    const float* Wx     = (const float*)d_in[6];   // (1024,1024)
    const float* Wh     = (const float*)d_in[7];   // (1024,1024)
    const float* b_rnn  = (const float*)d_in[8];   // (1024)
    const float* W_post = (const float*)d_in[9];   // (1024,768)
    const float* b_post = (const float*)d_in[10];  // (768)

    float* out  = (float*)d_out;
    float* net  = out;                                   // (B,512)
    float* o2c  = out + (size_t)B_ * OUT_;               // (B,256)
    float* hnew = out + (size_t)B_ * (OUT_ + O2C_);      // (B,1024)

    float* wfused = nullptr;
    float* rnn    = nullptr;
    cudaGetSymbolAddress((void**)&wfused, g_wfused);
    cudaGetSymbolAddress((void**)&rnn, g_rnn);

    // 1) scale = 1/max(||W_read||,1)
    norm_kernel<<<1, 256>>>(W_read);

    // 2) W_fused[512,1024] = scale * W_read[512,256] @ W_pre[512:768, :]
    gemm_dual<EPI_SCALE><<<dim3(FF_ / BN, CENTER_ / BM), 256>>>(
        W_read, CTX_, W_pre + (size_t)IN_ * FF_, CTX_,
        nullptr, 0, nullptr, 0,
        nullptr, wfused, nullptr, FF_, 0);

    // 3) rnn_in = relu(inputs @ W_pre[:512,:] + center @ W_fused + b_pre)
    gemm_dual<EPI_RELU><<<dim3(FF_ / BN, B_ / BM), 256>>>(
        inputs, IN_, W_pre, IN_,
        center, CENTER_, wfused, CENTER_,
        b_pre, rnn, nullptr, FF_, 0);

    // 4) h_new = tanh(rnn_in @ Wx + module_state @ Wh + b_rnn)  -> output slot
    gemm_dual<EPI_TANH><<<dim3(RNN_ / BN, B_ / BM), 256>>>(
        rnn, FF_, Wx, FF_,
        mstate, RNN_, Wh, RNN_,
        b_rnn, hnew, nullptr, RNN_, 0);

    // 5) module_output = relu(h_new @ W_post + b_post), split into net / o2c
    gemm_dual<EPI_RELU_SPLIT><<<dim3(TOT_ / BN, B_ / BM), 256>>>(
        hnew, RNN_, W_post, RNN_,
        nullptr, 0, nullptr, 0,
        b_post, net, o2c, TOT_, OUT_);
}

// round 4
// speedup vs baseline: 1.7997x; 1.7997x over previous
#include <cuda_runtime.h>
#include <cstdint>
#include <math.h>

// ---------------------------------------------------------------------------
// Problem constants
// ---------------------------------------------------------------------------
#define B_      8192
#define IN_     512
#define CTX_    256
#define CENTER_ 512
#define FF_     1024
#define RNN_    1024
#define OUT_    512
#define O2C_    256
#define TOT_    768

// ---------------------------------------------------------------------------
// Scratch (__device__ globals; allocation-free rule)
// ---------------------------------------------------------------------------
__device__ float g_scale;
__device__ float g_WpreT [FF_ * (IN_ + CTX_)];  // [1024][768]
__device__ float g_WxT   [RNN_ * FF_];          // [1024][1024]
__device__ float g_WhT   [RNN_ * RNN_];         // [1024][1024]
__device__ float g_WpostT[TOT_ * RNN_];         // [768][1024]
__device__ float g_WfT   [FF_ * CENTER_];       // [1024][512]
__device__ float g_rnn   [(size_t)B_ * FF_];    // rnn_in

// ---------------------------------------------------------------------------
// Small helpers
// ---------------------------------------------------------------------------
__device__ __forceinline__ uint32_t f2tf32(float x) {
    uint32_t o;
    asm("cvt.rna.tf32.f32 %0, %1;" : "=r"(o) : "f"(x));
    return o;
}
__device__ __forceinline__ void mma8(float* c, const uint32_t* a, const uint32_t* b) {
    asm volatile(
        "mma.sync.aligned.m16n8k8.row.col.f32.tf32.tf32.f32 "
        "{%0,%1,%2,%3}, {%4,%5,%6,%7}, {%8,%9}, {%0,%1,%2,%3};"
        : "+f"(c[0]), "+f"(c[1]), "+f"(c[2]), "+f"(c[3])
        : "r"(a[0]), "r"(a[1]), "r"(a[2]), "r"(a[3]), "r"(b[0]), "r"(b[1]));
}
__device__ __forceinline__ float fast_tanh(float x) {
    // tanh(x) = 2/(1+exp(-2x)) - 1 ; exp via ex2.approx, rcp.approx
    float e;
    asm("ex2.approx.f32 %0, %1;" : "=f"(e) : "f"(x * -2.885390081777927f)); // -2*log2(e)*x
    float r;
    asm("rcp.approx.f32 %0, %1;" : "=f"(r) : "f"(1.0f + e));
    return fmaf(2.0f, r, -1.0f);
}

// ---------------------------------------------------------------------------
// Norm: g_scale = 1 / max(||W_read||_F, 1)
// ---------------------------------------------------------------------------
__global__ void norm_kernel(const float* __restrict__ W) {
    __shared__ double red[256];
    double s = 0.0;
    for (int i = threadIdx.x; i < CENTER_ * CTX_; i += 256) {
        float v = W[i];
        s += (double)v * (double)v;
    }
    red[threadIdx.x] = s;
    __syncthreads();
    for (int o = 128; o > 0; o >>= 1) {
        if (threadIdx.x < o) red[threadIdx.x] += red[threadIdx.x + o];
        __syncthreads();
    }
    if (threadIdx.x == 0) g_scale = 1.0f / fmaxf((float)sqrt(red[0]), 1.0f);
}

// ---------------------------------------------------------------------------
// Transpose: dst[C,R] = src[R,C]^T
// ---------------------------------------------------------------------------
__global__ void transpose_kernel(const float* __restrict__ src, float* __restrict__ dst,
                                 int R, int C) {
    __shared__ float t[32][33];
    int bx = blockIdx.x * 32, by = blockIdx.y * 32;
#pragma unroll
    for (int i = 0; i < 32; i += 8)
        t[threadIdx.y + i][threadIdx.x] = src[(size_t)(by + threadIdx.y + i) * C + bx + threadIdx.x];
    __syncthreads();
#pragma unroll
    for (int i = 0; i < 32; i += 8)
        dst[(size_t)(bx + threadIdx.y + i) * R + by + threadIdx.x] = t[threadIdx.x][threadIdx.y + i];
}

// ---------------------------------------------------------------------------
// tf32 mma.sync dual-segment GEMM: D[M,N] = epi( A0@B0^T + A1@B1^T + bias )
//   A [M,K] row-major fp32, B^T [N,K] row-major fp32.
//   BM=128, BN=256, KS=32; 256 threads; 8 warps as 2(M)x4(N); warp tile 64x64.
//   SMEM swizzle: float col' = col ^ ((row&7)<<2); conflict-free STS.128 +
//   conflict-free 32-bit fragment loads.
// ---------------------------------------------------------------------------
#define BM 128
#define BN 256
#define KS 32
#define A_FLOATS   (BM * KS)            // 4096
#define STAGE_FLOATS ((BM + BN) * KS)   // 12288
#define SMEM_BYTES (2 * STAGE_FLOATS * 4)  // 98304

#define EPI_SCALE      0
#define EPI_RELU       1
#define EPI_TANH       2
#define EPI_RELU_SPLIT 3

__device__ __forceinline__ void stage_ldg(const float* __restrict__ A, int lda,
                                          const float* __restrict__ Bt, int ldb,
                                          int rowBase, int colBase, int kb, int tid,
                                          float4* ra, float4* rb) {
    const int ar = tid >> 1, aq0 = (tid & 1) * 4;
    const float* ap = A + (size_t)(rowBase + ar) * lda + kb;
#pragma unroll
    for (int i = 0; i < 4; i++) ra[i] = *(const float4*)(ap + 4 * (aq0 + i));
    const float* bp = Bt + (size_t)(colBase + tid) * ldb + kb;
#pragma unroll
    for (int i = 0; i < 8; i++) rb[i] = *(const float4*)(bp + 4 * i);
}

__device__ __forceinline__ void stage_sts(uint32_t* __restrict__ As, uint32_t* __restrict__ Bs,
                                          int tid, const float4* ra, const float4* rb) {
    const int ar = tid >> 1, aq0 = (tid & 1) * 4;
#pragma unroll
    for (int i = 0; i < 4; i++) {
        uint4 t;
        t.x = f2tf32(ra[i].x); t.y = f2tf32(ra[i].y);
        t.z = f2tf32(ra[i].z); t.w = f2tf32(ra[i].w);
        *(uint4*)&As[ar * 32 + 4 * ((aq0 + i) ^ (ar & 7))] = t;
    }
#pragma unroll
    for (int i = 0; i < 8; i++) {
        uint4 t;
        t.x = f2tf32(rb[i].x); t.y = f2tf32(rb[i].y);
        t.z = f2tf32(rb[i].z); t.w = f2tf32(rb[i].w);
        *(uint4*)&Bs[tid * 32 + 4 * (i ^ (tid & 7))] = t;
    }
}

template <int EPI>
__global__ __launch_bounds__(256)
void tgemm(const float* __restrict__ A0, int lda0, const float* __restrict__ B0, int ldb0, int K0,
           const float* __restrict__ A1, int lda1, const float* __restrict__ B1, int ldb1, int K1,
           const float* __restrict__ bias,
           float* __restrict__ C0, float* __restrict__ C1, int NC, int splitN)
{
    extern __shared__ uint32_t smem[];
    const int tid = threadIdx.x;
    const int wid = tid >> 5;
    const int lid = tid & 31;
    const int g   = lid >> 2;       // group id 0..7
    const int tig = lid & 3;        // thread-in-group 0..3
    const int wm  = wid >> 2;       // 0..1  (M)
    const int wn  = wid & 3;        // 0..3  (N)
    const int rowBase = blockIdx.y * BM;
    const int colBase = blockIdx.x * BN;

    const int S0 = K0 / KS, S1 = K1 / KS, S = S0 + S1;

    float c[128];
#pragma unroll
    for (int i = 0; i < 128; i++) c[i] = 0.0f;

    // Prologue: stage 0
    {
        float4 ra[4], rb[8];
        stage_ldg(A0, lda0, B0, ldb0, rowBase, colBase, 0, tid, ra, rb);
        stage_sts(smem, smem + A_FLOATS, tid, ra, rb);
    }
    __syncthreads();

    for (int s = 0; s < S; s++) {
        const int buf = s & 1;
        const uint32_t* As = smem + buf * STAGE_FLOATS;
        const uint32_t* Bs = As + A_FLOATS;

        // Issue next stage's global loads early (latency hidden by compute)
        float4 ra[4], rb[8];
        const bool more = (s + 1 < S);
        if (more) {
            const int ns = s + 1;
            if (ns < S0) stage_ldg(A0, lda0, B0, ldb0, rowBase, colBase, ns * KS, tid, ra, rb);
            else         stage_ldg(A1, lda1, B1, ldb1, rowBase, colBase, (ns - S0) * KS, tid, ra, rb);
        }

        // Compute 4 k-steps on current buffer
#pragma unroll
        for (int j = 0; j < 4; j++) {
            const int colX = (8 * j + tig) ^ (g << 2);
            const int colY = colX ^ 4;
            uint32_t af[4][4], bf[8][2];
#pragma unroll
            for (int t = 0; t < 4; t++) {
                const int r0 = wm * 64 + t * 16 + g;
                af[t][0] = As[r0 * 32 + colX];
                af[t][1] = As[(r0 + 8) * 32 + colX];
                af[t][2] = As[r0 * 32 + colY];
                af[t][3] = As[(r0 + 8) * 32 + colY];
            }
#pragma unroll
            for (int u = 0; u < 8; u++) {
                const int n0 = wn * 64 + u * 8 + g;
                bf[u][0] = Bs[n0 * 32 + colX];
                bf[u][1] = Bs[n0 * 32 + colY];
            }
#pragma unroll
            for (int t = 0; t < 4; t++)
#pragma unroll
                for (int u = 0; u < 8; u++)
                    mma8(&c[(t * 8 + u) * 4], af[t], bf[u]);
        }

        if (more) {
            uint32_t* Ad = smem + (buf ^ 1) * STAGE_FLOATS;
            stage_sts(Ad, Ad + A_FLOATS, tid, ra, rb);
        }
        __syncthreads();
    }

    // Epilogue (accumulators -> gmem)
    const float scale = (EPI == EPI_SCALE) ? g_scale : 0.0f;
#pragma unroll
    for (int t = 0; t < 4; t++) {
        const int row0 = rowBase + wm * 64 + t * 16 + g;
#pragma unroll
        for (int u = 0; u < 8; u++) {
            const int col = colBase + wn * 64 + u * 8 + 2 * tig;
            float v0 = c[(t * 8 + u) * 4 + 0];
            float v1 = c[(t * 8 + u) * 4 + 1];
            float v2 = c[(t * 8 + u) * 4 + 2];
            float v3 = c[(t * 8 + u) * 4 + 3];
            if (EPI == EPI_SCALE) {
                v0 *= scale; v1 *= scale; v2 *= scale; v3 *= scale;
                *(float2*)&C0[(size_t)row0 * NC + col]       = make_float2(v0, v1);
                *(float2*)&C0[(size_t)(row0 + 8) * NC + col] = make_float2(v2, v3);
            } else {
                const float b0 = bias[col], b1 = bias[col + 1];
                v0 += b0; v1 += b1; v2 += b0; v3 += b1;
                if (EPI == EPI_RELU) {
                    v0 = fmaxf(v0, 0.0f); v1 = fmaxf(v1, 0.0f);
                    v2 = fmaxf(v2, 0.0f); v3 = fmaxf(v3, 0.0f);
                    *(float2*)&C0[(size_t)row0 * NC + col]       = make_float2(v0, v1);
                    *(float2*)&C0[(size_t)(row0 + 8) * NC + col] = make_float2(v2, v3);
                } else if (EPI == EPI_TANH) {
                    v0 = fast_tanh(v0); v1 = fast_tanh(v1);
                    v2 = fast_tanh(v2); v3 = fast_tanh(v3);
                    *(float2*)&C0[(size_t)row0 * NC + col]       = make_float2(v0, v1);
                    *(float2*)&C0[(size_t)(row0 + 8) * NC + col] = make_float2(v2, v3);
                } else { // EPI_RELU_SPLIT
                    v0 = fmaxf(v0, 0.0f); v1 = fmaxf(v1, 0.0f);
                    v2 = fmaxf(v2, 0.0f); v3 = fmaxf(v3, 0.0f);
                    if (col < splitN) {
                        *(float2*)&C0[(size_t)row0 * splitN + col]       = make_float2(v0, v1);
                        *(float2*)&C0[(size_t)(row0 + 8) * splitN + col] = make_float2(v2, v3);
                    } else {
                        const int c2 = col - splitN, w2 = NC - splitN;
                        *(float2*)&C1[(size_t)row0 * w2 + c2]       = make_float2(v0, v1);
                        *(float2*)&C1[(size_t)(row0 + 8) * w2 + c2] = make_float2(v2, v3);
                    }
                }
            }
        }
    }
}

// ---------------------------------------------------------------------------
// Launch
// ---------------------------------------------------------------------------
extern "C" void kernel_launch(void* const* d_in, const int* in_sizes, int n_in,
                              void* d_out, int out_size)
{
    const float* inputs = (const float*)d_in[0];
    const float* center = (const float*)d_in[1];
    const float* mstate = (const float*)d_in[2];
    const float* W_read = (const float*)d_in[3];
    const float* W_pre  = (const float*)d_in[4];
    const float* b_pre  = (const float*)d_in[5];
    const float* Wx     = (const float*)d_in[6];
    const float* Wh     = (const float*)d_in[7];
    const float* b_rnn  = (const float*)d_in[8];
    const float* W_post = (const float*)d_in[9];
    const float* b_post = (const float*)d_in[10];

    float* out  = (float*)d_out;
    float* net  = out;
    float* o2c  = out + (size_t)B_ * OUT_;
    float* hnew = out + (size_t)B_ * (OUT_ + O2C_);

    float *WpreT, *WxT, *WhT, *WpostT, *WfT, *rnn;
    cudaGetSymbolAddress((void**)&WpreT,  g_WpreT);
    cudaGetSymbolAddress((void**)&WxT,    g_WxT);
    cudaGetSymbolAddress((void**)&WhT,    g_WhT);
    cudaGetSymbolAddress((void**)&WpostT, g_WpostT);
    cudaGetSymbolAddress((void**)&WfT,    g_WfT);
    cudaGetSymbolAddress((void**)&rnn,    g_rnn);

    cudaFuncSetAttribute(tgemm<EPI_SCALE>,      cudaFuncAttributeMaxDynamicSharedMemorySize, SMEM_BYTES);
    cudaFuncSetAttribute(tgemm<EPI_RELU>,       cudaFuncAttributeMaxDynamicSharedMemorySize, SMEM_BYTES);
    cudaFuncSetAttribute(tgemm<EPI_TANH>,       cudaFuncAttributeMaxDynamicSharedMemorySize, SMEM_BYTES);
    cudaFuncSetAttribute(tgemm<EPI_RELU_SPLIT>, cudaFuncAttributeMaxDynamicSharedMemorySize, SMEM_BYTES);

    dim3 tb(32, 8);

    norm_kernel<<<1, 256>>>(W_read);

    transpose_kernel<<<dim3(FF_ / 32, (IN_ + CTX_) / 32), tb>>>(W_pre,  WpreT,  IN_ + CTX_, FF_);
    transpose_kernel<<<dim3(RNN_ / 32, FF_ / 32),  tb>>>(Wx,     WxT,    FF_,  RNN_);
    transpose_kernel<<<dim3(RNN_ / 32, RNN_ / 32), tb>>>(Wh,     WhT,    RNN_, RNN_);
    transpose_kernel<<<dim3(TOT_ / 32, RNN_ / 32), tb>>>(W_post, WpostT, RNN_, TOT_);

    // WfT[ff][c] = scale * sum_j WpreT[ff][512+j] * W_read[c][j]  (M=1024,N=512,K=256)
    tgemm<EPI_SCALE><<<dim3(CENTER_ / BN, FF_ / BM), 256, SMEM_BYTES>>>(
        WpreT + IN_, IN_ + CTX_, W_read, CTX_, CTX_,
        nullptr, 0, nullptr, 0, 0,
        nullptr, WfT, nullptr, CENTER_, 0);

    // rnn_in = relu(inputs@Wpre[:512] + center@Wf + b_pre)  (M=8192,N=1024,K=512+512)
    tgemm<EPI_RELU><<<dim3(FF_ / BN, B_ / BM), 256, SMEM_BYTES>>>(
        inputs, IN_, WpreT, IN_ + CTX_, IN_,
        center, CENTER_, WfT, CENTER_, CENTER_,
        b_pre, rnn, nullptr, FF_, 0);

    // h_new = tanh(rnn@Wx + mstate@Wh + b_rnn)  (M=8192,N=1024,K=1024+1024)
    tgemm<EPI_TANH><<<dim3(RNN_ / BN, B_ / BM), 256, SMEM_BYTES>>>(
        rnn, FF_, WxT, FF_, FF_,
        mstate, RNN_, WhT, RNN_, RNN_,
        b_rnn, hnew, nullptr, RNN_, 0);

    // module_output = relu(h_new@W_post + b_post), split  (M=8192,N=768,K=1024)
    tgemm<EPI_RELU_SPLIT><<<dim3(TOT_ / BN, B_ / BM), 256, SMEM_BYTES>>>(
        hnew, RNN_, WpostT, RNN_, RNN_,
        nullptr, 0, nullptr, 0, 0,
        b_post, net, o2c, TOT_, OUT_);
}

// round 6
// speedup vs baseline: 2.0688x; 1.1495x over previous
#include <cuda_runtime.h>
#include <cstdint>
#include <math.h>

// ---------------------------------------------------------------------------
// Problem constants
// ---------------------------------------------------------------------------
#define B_      8192
#define IN_     512
#define CTX_    256
#define CENTER_ 512
#define FF_     1024
#define RNN_    1024
#define OUT_    512
#define O2C_    256
#define TOT_    768

// ---------------------------------------------------------------------------
// Scratch (__device__ globals; allocation-free rule)
// ---------------------------------------------------------------------------
__device__ float g_scale;
__device__ float g_WpreT [FF_ * (IN_ + CTX_)];  // [1024][768]  tf32-rounded
__device__ float g_WxT   [RNN_ * FF_];          // [1024][1024] tf32-rounded
__device__ float g_WhT   [RNN_ * RNN_];         // [1024][1024] tf32-rounded
__device__ float g_WpostT[TOT_ * RNN_];         // [768][1024]  tf32-rounded
__device__ float g_WfT   [FF_ * CENTER_];       // [1024][512]  tf32-rounded
__device__ float g_WreadTf[CENTER_ * CTX_];     // [512][256]   tf32-rounded
__device__ float g_inTf  [(size_t)B_ * IN_];
__device__ float g_ctrTf [(size_t)B_ * CENTER_];
__device__ float g_mstTf [(size_t)B_ * RNN_];
__device__ float g_rnn   [(size_t)B_ * FF_];    // rnn_in (tf32-rounded)

// ---------------------------------------------------------------------------
// Helpers
// ---------------------------------------------------------------------------
__device__ __forceinline__ uint32_t smem_u32(const void* p) {
    uint32_t a;
    asm("{ .reg .u64 t; cvta.to.shared.u64 t, %1; cvt.u32.u64 %0, t; }" : "=r"(a) : "l"(p));
    return a;
}
__device__ __forceinline__ uint32_t f2tf32(float x) {
    uint32_t o;
    asm("cvt.rna.tf32.f32 %0, %1;" : "=r"(o) : "f"(x));
    return o;
}
__device__ __forceinline__ void mma8(float* c, const uint32_t* a, const uint32_t* b) {
    asm volatile(
        "mma.sync.aligned.m16n8k8.row.col.f32.tf32.tf32.f32 "
        "{%0,%1,%2,%3}, {%4,%5,%6,%7}, {%8,%9}, {%0,%1,%2,%3};"
        : "+f"(c[0]), "+f"(c[1]), "+f"(c[2]), "+f"(c[3])
        : "r"(a[0]), "r"(a[1]), "r"(a[2]), "r"(a[3]), "r"(b[0]), "r"(b[1]));
}
__device__ __forceinline__ float fast_tanh(float x) {
    float e;
    asm("ex2.approx.f32 %0, %1;" : "=f"(e) : "f"(x * -2.885390081777927f));
    float r;
    asm("rcp.approx.f32 %0, %1;" : "=f"(r) : "f"(1.0f + e));
    return fmaf(2.0f, r, -1.0f);
}
#define CP_ASYNC16(sa, gp) \
    asm volatile("cp.async.cg.shared.global [%0], [%1], 16;" :: "r"(sa), "l"(gp))
#define CP_COMMIT() asm volatile("cp.async.commit_group;" ::: "memory")
#define CP_WAIT(N)  asm volatile("cp.async.wait_group %0;" :: "n"(N) : "memory")

// ---------------------------------------------------------------------------
// Norm: g_scale = 1 / max(||W_read||_F, 1)
// ---------------------------------------------------------------------------
__global__ void norm_kernel(const float* __restrict__ W) {
    __shared__ double red[256];
    double s = 0.0;
    for (int i = threadIdx.x; i < CENTER_ * CTX_; i += 256) {
        float v = W[i];
        s += (double)v * (double)v;
    }
    red[threadIdx.x] = s;
    __syncthreads();
    for (int o = 128; o > 0; o >>= 1) {
        if (threadIdx.x < o) red[threadIdx.x] += red[threadIdx.x + o];
        __syncthreads();
    }
    if (threadIdx.x == 0) g_scale = 1.0f / fmaxf((float)sqrt(red[0]), 1.0f);
}

// ---------------------------------------------------------------------------
// Elementwise tf32 rounding (float4 vectorized)
// ---------------------------------------------------------------------------
__global__ void tf32_convert(const float* __restrict__ src, float* __restrict__ dst, int n4) {
    int i = blockIdx.x * blockDim.x + threadIdx.x;
    if (i < n4) {
        float4 v = ((const float4*)src)[i];
        uint4 t;
        t.x = f2tf32(v.x); t.y = f2tf32(v.y); t.z = f2tf32(v.z); t.w = f2tf32(v.w);
        ((uint4*)dst)[i] = t;
    }
}

// ---------------------------------------------------------------------------
// Transpose with tf32 rounding: dst[C,R] = round(src[R,C]^T)
// ---------------------------------------------------------------------------
__global__ void transpose_kernel(const float* __restrict__ src, float* __restrict__ dst,
                                 int R, int C) {
    __shared__ float t[32][33];
    int bx = blockIdx.x * 32, by = blockIdx.y * 32;
#pragma unroll
    for (int i = 0; i < 32; i += 8)
        t[threadIdx.y + i][threadIdx.x] = src[(size_t)(by + threadIdx.y + i) * C + bx + threadIdx.x];
    __syncthreads();
#pragma unroll
    for (int i = 0; i < 32; i += 8)
        dst[(size_t)(bx + threadIdx.y + i) * R + by + threadIdx.x] =
            __uint_as_float(f2tf32(t[threadIdx.x][threadIdx.y + i]));
}

// ---------------------------------------------------------------------------
// tf32 mma.sync dual-segment GEMM (cp.async 3-stage pipeline)
//   D[M,N] = epi( A0@B0^T + A1@B1^T + bias )
//   A [M,K] row-major fp32 (tf32-clean), B^T [N,K] row-major fp32 (tf32-clean)
//   BM=128, BN=256, KS=32; 256 threads; 8 warps 2(M)x4(N); warp tile 64x64.
//   Swizzle (float granularity): col' = col ^ ((row&7)<<2)
// ---------------------------------------------------------------------------
#define BM 128
#define BN 256
#define KS 32
#define A_FLOATS     (BM * KS)            // 4096
#define STAGE_FLOATS ((BM + BN) * KS)     // 12288
#define STAGE_BYTES  (STAGE_FLOATS * 4)   // 49152
#define NSTAGE 3
#define SMEM_BYTES (NSTAGE * STAGE_BYTES) // 147456

#define EPI_SCALE      0
#define EPI_RELU       1
#define EPI_TANH       2
#define EPI_RELU_SPLIT 3

template <int EPI>
__global__ __launch_bounds__(256, 1)
void tgemm(const float* __restrict__ A0, int lda0, const float* __restrict__ B0, int ldb0, int K0,
           const float* __restrict__ A1, int lda1, const float* __restrict__ B1, int ldb1, int K1,
           const float* __restrict__ bias,
           float* __restrict__ C0, float* __restrict__ C1, int NC, int splitN)
{
    extern __shared__ uint32_t smem[];
    const uint32_t sb = smem_u32(smem);

    const int tid = threadIdx.x;
    const int wid = tid >> 5;
    const int lid = tid & 31;
    const int g   = lid >> 2;
    const int tig = lid & 3;
    const int wm  = wid >> 2;
    const int wn  = wid & 3;
    const int rowBase = blockIdx.y * BM;
    const int colBase = blockIdx.x * BN;

    const int S0 = K0 / KS, S1 = K1 / KS, S = S0 + S1;

    // Per-thread fixed SMEM byte offsets (within a stage buffer)
    const int ar = tid >> 1, aq0 = (tid & 1) * 4;
    uint32_t a_off[4], b_off[8];
#pragma unroll
    for (int i = 0; i < 4; i++)
        a_off[i] = (uint32_t)(ar * 32 + 4 * ((aq0 + i) ^ (ar & 7))) * 4u;
#pragma unroll
    for (int i = 0; i < 8; i++)
        b_off[i] = (uint32_t)(A_FLOATS + tid * 32 + 4 * (i ^ (tid & 7))) * 4u;

    auto issue = [&](int ns, int buf) {
        const float* A; const float* Bt; int la, lb, kb;
        if (ns < S0) { A = A0; Bt = B0; la = lda0; lb = ldb0; kb = ns * KS; }
        else         { A = A1; Bt = B1; la = lda1; lb = ldb1; kb = (ns - S0) * KS; }
        const float* ap = A + (size_t)(rowBase + ar) * la + kb + aq0 * 4;
        const float* bp = Bt + (size_t)(colBase + tid) * lb + kb;
        const uint32_t base = sb + (uint32_t)buf * STAGE_BYTES;
#pragma unroll
        for (int i = 0; i < 4; i++) CP_ASYNC16(base + a_off[i], ap + 4 * i);
#pragma unroll
        for (int i = 0; i < 8; i++) CP_ASYNC16(base + b_off[i], bp + 4 * i);
    };

    float c[128];
#pragma unroll
    for (int i = 0; i < 128; i++) c[i] = 0.0f;

    // Prologue: stages 0 and 1 in flight
    issue(0, 0); CP_COMMIT();
    issue(1, 1); CP_COMMIT();

    for (int s = 0; s < S; s++) {
        const int buf = s % NSTAGE;
        CP_WAIT(1);            // stage s landed
        __syncthreads();       // all warps done with buffer (s+2)%3 from iter s-1

        if (s + 2 < S) issue(s + 2, (s + 2) % NSTAGE);
        CP_COMMIT();           // commit (possibly empty) group to keep counts aligned

        const uint32_t* As = smem + buf * STAGE_FLOATS;
        const uint32_t* Bs = As + A_FLOATS;

#pragma unroll
        for (int j = 0; j < 4; j++) {
            const int colX = (8 * j + tig) ^ (g << 2);
            const int colY = colX ^ 4;
            uint32_t af[4][4], bf[8][2];
#pragma unroll
            for (int t = 0; t < 4; t++) {
                const int r0 = wm * 64 + t * 16 + g;
                af[t][0] = As[r0 * 32 + colX];
                af[t][1] = As[(r0 + 8) * 32 + colX];
                af[t][2] = As[r0 * 32 + colY];
                af[t][3] = As[(r0 + 8) * 32 + colY];
            }
#pragma unroll
            for (int u = 0; u < 8; u++) {
                const int n0 = wn * 64 + u * 8 + g;
                bf[u][0] = Bs[n0 * 32 + colX];
                bf[u][1] = Bs[n0 * 32 + colY];
            }
#pragma unroll
            for (int t = 0; t < 4; t++)
#pragma unroll
                for (int u = 0; u < 8; u++)
                    mma8(&c[(t * 8 + u) * 4], af[t], bf[u]);
        }
        __syncthreads();
    }

    // Epilogue. Round to tf32 when the result feeds another GEMM.
    constexpr bool ROUND = (EPI != EPI_RELU_SPLIT);
    const float scale = (EPI == EPI_SCALE) ? g_scale : 0.0f;
#pragma unroll
    for (int t = 0; t < 4; t++) {
        const int row0 = rowBase + wm * 64 + t * 16 + g;
#pragma unroll
        for (int u = 0; u < 8; u++) {
            const int col = colBase + wn * 64 + u * 8 + 2 * tig;
            float v0 = c[(t * 8 + u) * 4 + 0];
            float v1 = c[(t * 8 + u) * 4 + 1];
            float v2 = c[(t * 8 + u) * 4 + 2];
            float v3 = c[(t * 8 + u) * 4 + 3];
            if (EPI == EPI_SCALE) {
                v0 *= scale; v1 *= scale; v2 *= scale; v3 *= scale;
            } else {
                const float b0 = bias[col], b1 = bias[col + 1];
                v0 += b0; v1 += b1; v2 += b0; v3 += b1;
                if (EPI == EPI_RELU || EPI == EPI_RELU_SPLIT) {
                    v0 = fmaxf(v0, 0.0f); v1 = fmaxf(v1, 0.0f);
                    v2 = fmaxf(v2, 0.0f); v3 = fmaxf(v3, 0.0f);
                } else { // EPI_TANH
                    v0 = fast_tanh(v0); v1 = fast_tanh(v1);
                    v2 = fast_tanh(v2); v3 = fast_tanh(v3);
                }
            }
            if (ROUND) {
                v0 = __uint_as_float(f2tf32(v0));
                v1 = __uint_as_float(f2tf32(v1));
                v2 = __uint_as_float(f2tf32(v2));
                v3 = __uint_as_float(f2tf32(v3));
            }
            if (EPI != EPI_RELU_SPLIT) {
                *(float2*)&C0[(size_t)row0 * NC + col]       = make_float2(v0, v1);
                *(float2*)&C0[(size_t)(row0 + 8) * NC + col] = make_float2(v2, v3);
            } else {
                if (col < splitN) {
                    *(float2*)&C0[(size_t)row0 * splitN + col]       = make_float2(v0, v1);
                    *(float2*)&C0[(size_t)(row0 + 8) * splitN + col] = make_float2(v2, v3);
                } else {
                    const int c2 = col - splitN, w2 = NC - splitN;
                    *(float2*)&C1[(size_t)row0 * w2 + c2]       = make_float2(v0, v1);
                    *(float2*)&C1[(size_t)(row0 + 8) * w2 + c2] = make_float2(v2, v3);
                }
            }
        }
    }
}

// ---------------------------------------------------------------------------
// Launch
// ---------------------------------------------------------------------------
extern "C" void kernel_launch(void* const* d_in, const int* in_sizes, int n_in,
                              void* d_out, int out_size)
{
    const float* inputs = (const float*)d_in[0];
    const float* center = (const float*)d_in[1];
    const float* mstate = (const float*)d_in[2];
    const float* W_read = (const float*)d_in[3];
    const float* W_pre  = (const float*)d_in[4];
    const float* b_pre  = (const float*)d_in[5];
    const float* Wx     = (const float*)d_in[6];
    const float* Wh     = (const float*)d_in[7];
    const float* b_rnn  = (const float*)d_in[8];
    const float* W_post = (const float*)d_in[9];
    const float* b_post = (const float*)d_in[10];

    float* out  = (float*)d_out;
    float* net  = out;
    float* o2c  = out + (size_t)B_ * OUT_;
    float* hnew = out + (size_t)B_ * (OUT_ + O2C_);

    float *WpreT, *WxT, *WhT, *WpostT, *WfT, *WreadTf, *inTf, *ctrTf, *mstTf, *rnn;
    cudaGetSymbolAddress((void**)&WpreT,   g_WpreT);
    cudaGetSymbolAddress((void**)&WxT,     g_WxT);
    cudaGetSymbolAddress((void**)&WhT,     g_WhT);
    cudaGetSymbolAddress((void**)&WpostT,  g_WpostT);
    cudaGetSymbolAddress((void**)&WfT,     g_WfT);
    cudaGetSymbolAddress((void**)&WreadTf, g_WreadTf);
    cudaGetSymbolAddress((void**)&inTf,    g_inTf);
    cudaGetSymbolAddress((void**)&ctrTf,   g_ctrTf);
    cudaGetSymbolAddress((void**)&mstTf,   g_mstTf);
    cudaGetSymbolAddress((void**)&rnn,     g_rnn);

    cudaFuncSetAttribute(tgemm<EPI_SCALE>,      cudaFuncAttributeMaxDynamicSharedMemorySize, SMEM_BYTES);
    cudaFuncSetAttribute(tgemm<EPI_RELU>,       cudaFuncAttributeMaxDynamicSharedMemorySize, SMEM_BYTES);
    cudaFuncSetAttribute(tgemm<EPI_TANH>,       cudaFuncAttributeMaxDynamicSharedMemorySize, SMEM_BYTES);
    cudaFuncSetAttribute(tgemm<EPI_RELU_SPLIT>, cudaFuncAttributeMaxDynamicSharedMemorySize, SMEM_BYTES);

    dim3 tb(32, 8);

    norm_kernel<<<1, 256>>>(W_read);

    // tf32 pre-rounding of activations + W_read
    tf32_convert<<<(B_ * IN_ / 4 + 255) / 256, 256>>>(inputs, inTf, B_ * IN_ / 4);
    tf32_convert<<<(B_ * CENTER_ / 4 + 255) / 256, 256>>>(center, ctrTf, B_ * CENTER_ / 4);
    tf32_convert<<<(B_ * RNN_ / 4 + 255) / 256, 256>>>(mstate, mstTf, B_ * RNN_ / 4);
    tf32_convert<<<(CENTER_ * CTX_ / 4 + 255) / 256, 256>>>(W_read, WreadTf, CENTER_ * CTX_ / 4);

    // Weight transposes (rounded on store)
    transpose_kernel<<<dim3(FF_ / 32, (IN_ + CTX_) / 32), tb>>>(W_pre,  WpreT,  IN_ + CTX_, FF_);
    transpose_kernel<<<dim3(RNN_ / 32, FF_ / 32),  tb>>>(Wx,     WxT,    FF_,  RNN_);
    transpose_kernel<<<dim3(RNN_ / 32, RNN_ / 32), tb>>>(Wh,     WhT,    RNN_, RNN_);
    transpose_kernel<<<dim3(TOT_ / 32, RNN_ / 32), tb>>>(W_post, WpostT, RNN_, TOT_);

    // WfT = scale * (WpreT_ctx @ W_read^T)   (M=1024, N=512, K=256)
    tgemm<EPI_SCALE><<<dim3(CENTER_ / BN, FF_ / BM), 256, SMEM_BYTES>>>(
        WpreT + IN_, IN_ + CTX_, WreadTf, CTX_, CTX_,
        nullptr, 0, nullptr, 0, 0,
        nullptr, WfT, nullptr, CENTER_, 0);

    // rnn_in = relu(inputs@Wpre[:512] + center@Wf + b_pre)  (M=8192,N=1024,K=512+512)
    tgemm<EPI_RELU><<<dim3(FF_ / BN, B_ / BM), 256, SMEM_BYTES>>>(
        inTf, IN_, WpreT, IN_ + CTX_, IN_,
        ctrTf, CENTER_, WfT, CENTER_, CENTER_,
        b_pre, rnn, nullptr, FF_, 0);

    // h_new = tanh(rnn@Wx + mstate@Wh + b_rnn)  (M=8192,N=1024,K=1024+1024)
    tgemm<EPI_TANH><<<dim3(RNN_ / BN, B_ / BM), 256, SMEM_BYTES>>>(
        rnn, FF_, WxT, FF_, FF_,
        mstTf, RNN_, WhT, RNN_, RNN_,
        b_rnn, hnew, nullptr, RNN_, 0);

    // module_output = relu(h_new@W_post + b_post), split  (M=8192,N=768,K=1024)
    tgemm<EPI_RELU_SPLIT><<<dim3(TOT_ / BN, B_ / BM), 256, SMEM_BYTES>>>(
        hnew, RNN_, WpostT, RNN_, RNN_,
        nullptr, 0, nullptr, 0, 0,
        b_post, net, o2c, TOT_, OUT_);
}

// round 8
// speedup vs baseline: 2.7253x; 1.3173x over previous
#include <cuda_runtime.h>
#include <cstdint>
#include <math.h>

// ---------------------------------------------------------------------------
// Problem constants
// ---------------------------------------------------------------------------
#define B_      8192
#define IN_     512
#define CTX_    256
#define CENTER_ 512
#define FF_     1024
#define RNN_    1024
#define OUT_    512
#define O2C_    256
#define TOT_    768

// ---------------------------------------------------------------------------
// Scratch (__device__ globals; allocation-free rule)
// ---------------------------------------------------------------------------
__device__ float  g_scale;
__device__ double g_npart[64];
__device__ float g_WpreT [FF_ * (IN_ + CTX_)];
__device__ float g_WxT   [RNN_ * FF_];
__device__ float g_WhT   [RNN_ * RNN_];
__device__ float g_WpostT[TOT_ * RNN_];
__device__ float g_WfT   [FF_ * CENTER_];
__device__ float g_WreadTf[CENTER_ * CTX_];
__device__ float g_inTf  [(size_t)B_ * IN_];
__device__ float g_ctrTf [(size_t)B_ * CENTER_];
__device__ float g_mstTf [(size_t)B_ * RNN_];
__device__ float g_rnn   [(size_t)B_ * FF_];

// ---------------------------------------------------------------------------
// Helpers
// ---------------------------------------------------------------------------
__device__ __forceinline__ uint32_t smem_u32(const void* p) {
    uint32_t a;
    asm("{ .reg .u64 t; cvta.to.shared.u64 t, %1; cvt.u32.u64 %0, t; }" : "=r"(a) : "l"(p));
    return a;
}
__device__ __forceinline__ uint32_t f2tf32(float x) {
    uint32_t o;
    asm("cvt.rna.tf32.f32 %0, %1;" : "=r"(o) : "f"(x));
    return o;
}
__device__ __forceinline__ void mma8(float* c, const uint32_t* a, const uint32_t* b) {
    asm volatile(
        "mma.sync.aligned.m16n8k8.row.col.f32.tf32.tf32.f32 "
        "{%0,%1,%2,%3}, {%4,%5,%6,%7}, {%8,%9}, {%0,%1,%2,%3};"
        : "+f"(c[0]), "+f"(c[1]), "+f"(c[2]), "+f"(c[3])
        : "r"(a[0]), "r"(a[1]), "r"(a[2]), "r"(a[3]), "r"(b[0]), "r"(b[1]));
}
__device__ __forceinline__ float fast_tanh(float x) {
    float e;
    asm("ex2.approx.f32 %0, %1;" : "=f"(e) : "f"(x * -2.885390081777927f));
    float r;
    asm("rcp.approx.f32 %0, %1;" : "=f"(r) : "f"(1.0f + e));
    return fmaf(2.0f, r, -1.0f);
}
#define CP_ASYNC16(sa, gp) \
    asm volatile("cp.async.cg.shared.global [%0], [%1], 16;" :: "r"(sa), "l"(gp))
#define CP_COMMIT() asm volatile("cp.async.commit_group;" ::: "memory")
#define CP_WAIT(N)  asm volatile("cp.async.wait_group %0;" :: "n"(N) : "memory")

// ---------------------------------------------------------------------------
// Norm (two-phase): g_scale = 1 / max(||W_read||_F, 1)
// ---------------------------------------------------------------------------
__global__ void norm_part(const float* __restrict__ W) {
    __shared__ double red[256];
    double s = 0.0;
    for (int i = blockIdx.x * 256 + threadIdx.x; i < CENTER_ * CTX_; i += 64 * 256) {
        float v = W[i];
        s += (double)v * (double)v;
    }
    red[threadIdx.x] = s;
    __syncthreads();
    for (int o = 128; o > 0; o >>= 1) {
        if (threadIdx.x < o) red[threadIdx.x] += red[threadIdx.x + o];
        __syncthreads();
    }
    if (threadIdx.x == 0) g_npart[blockIdx.x] = red[0];
}
__global__ void norm_fin() {
    __shared__ double red[64];
    red[threadIdx.x] = g_npart[threadIdx.x];
    __syncthreads();
    for (int o = 32; o > 0; o >>= 1) {
        if (threadIdx.x < o) red[threadIdx.x] += red[threadIdx.x + o];
        __syncthreads();
    }
    if (threadIdx.x == 0) g_scale = 1.0f / fmaxf((float)sqrt(red[0]), 1.0f);
}

// ---------------------------------------------------------------------------
// Elementwise tf32 rounding (float4 vectorized)
// ---------------------------------------------------------------------------
__global__ void tf32_convert(const float* __restrict__ src, float* __restrict__ dst, int n4) {
    int i = blockIdx.x * blockDim.x + threadIdx.x;
    if (i < n4) {
        float4 v = ((const float4*)src)[i];
        uint4 t;
        t.x = f2tf32(v.x); t.y = f2tf32(v.y); t.z = f2tf32(v.z); t.w = f2tf32(v.w);
        ((uint4*)dst)[i] = t;
    }
}

// ---------------------------------------------------------------------------
// Transpose with tf32 rounding: dst[C,R] = round(src[R,C]^T)
// ---------------------------------------------------------------------------
__global__ void transpose_kernel(const float* __restrict__ src, float* __restrict__ dst,
                                 int R, int C) {
    __shared__ float t[32][33];
    int bx = blockIdx.x * 32, by = blockIdx.y * 32;
#pragma unroll
    for (int i = 0; i < 32; i += 8)
        t[threadIdx.y + i][threadIdx.x] = src[(size_t)(by + threadIdx.y + i) * C + bx + threadIdx.x];
    __syncthreads();
#pragma unroll
    for (int i = 0; i < 32; i += 8)
        dst[(size_t)(bx + threadIdx.y + i) * R + by + threadIdx.x] =
            __uint_as_float(f2tf32(t[threadIdx.x][threadIdx.y + i]));
}

// ---------------------------------------------------------------------------
// tf32 mma.sync dual-segment GEMM (cp.async 3-stage pipeline, 512 threads)
//   D[M,N] = epi( A0@B0^T + A1@B1^T + bias )
//   BM=128, BN=256, KS=32; 16 warps as 4(M)x4(N); warp tile 32x64.
//   Swizzle (float granularity): col' = col ^ ((row&7)<<2)
// ---------------------------------------------------------------------------
#define BM 128
#define BN 256
#define KS 32
#define NTHREADS 512
#define A_FLOATS     (BM * KS)            // 4096
#define STAGE_FLOATS ((BM + BN) * KS)     // 12288
#define STAGE_BYTES  (STAGE_FLOATS * 4)   // 49152
#define NSTAGE 3
#define SMEM_BYTES (NSTAGE * STAGE_BYTES) // 147456

#define EPI_SCALE      0
#define EPI_RELU       1
#define EPI_TANH       2
#define EPI_RELU_SPLIT 3

template <int EPI>
__global__ __launch_bounds__(NTHREADS, 1)
void tgemm(const float* __restrict__ A0, int lda0, const float* __restrict__ B0, int ldb0, int K0,
           const float* __restrict__ A1, int lda1, const float* __restrict__ B1, int ldb1, int K1,
           const float* __restrict__ bias,
           float* __restrict__ C0, float* __restrict__ C1, int NC, int splitN)
{
    extern __shared__ uint32_t smem[];
    const uint32_t sb = smem_u32(smem);

    const int tid = threadIdx.x;
    const int wid = tid >> 5;
    const int lid = tid & 31;
    const int g   = lid >> 2;
    const int tig = lid & 3;
    const int wm  = wid >> 2;       // 0..3  (M)
    const int wn  = wid & 3;        // 0..3  (N)
    const int rowBase = blockIdx.y * BM;
    const int colBase = blockIdx.x * BN;

    const int S0 = K0 / KS, S1 = K1 / KS, S = S0 + S1;

    // Loader assignments (512 threads)
    const int ar = tid >> 2, aq0 = (tid & 3) * 2;   // A: 128 rows x 8 quads; 2 quads/thread
    const int br = tid >> 1, bq0 = (tid & 1) * 4;   // B: 256 rows x 8 quads; 4 quads/thread
    uint32_t a_off[2], b_off[4];
#pragma unroll
    for (int i = 0; i < 2; i++)
        a_off[i] = (uint32_t)(ar * 32 + 4 * ((aq0 + i) ^ (ar & 7))) * 4u;
#pragma unroll
    for (int i = 0; i < 4; i++)
        b_off[i] = (uint32_t)(A_FLOATS + br * 32 + 4 * ((bq0 + i) ^ (br & 7))) * 4u;

    auto issue = [&](int ns, int buf) {
        const float* A; const float* Bt; int la, lb, kb;
        if (ns < S0) { A = A0; Bt = B0; la = lda0; lb = ldb0; kb = ns * KS; }
        else         { A = A1; Bt = B1; la = lda1; lb = ldb1; kb = (ns - S0) * KS; }
        const float* ap = A + (size_t)(rowBase + ar) * la + kb + aq0 * 4;
        const float* bp = Bt + (size_t)(colBase + br) * lb + kb + bq0 * 4;
        const uint32_t base = sb + (uint32_t)buf * STAGE_BYTES;
#pragma unroll
        for (int i = 0; i < 2; i++) CP_ASYNC16(base + a_off[i], ap + 4 * i);
#pragma unroll
        for (int i = 0; i < 4; i++) CP_ASYNC16(base + b_off[i], bp + 4 * i);
    };

    float c[64];
#pragma unroll
    for (int i = 0; i < 64; i++) c[i] = 0.0f;

    // Prologue: stages 0 and 1 in flight
    issue(0, 0); CP_COMMIT();
    issue(1, 1); CP_COMMIT();

    for (int s = 0; s < S; s++) {
        const int buf = s % NSTAGE;
        CP_WAIT(1);
        __syncthreads();

        if (s + 2 < S) issue(s + 2, (s + 2) % NSTAGE);
        CP_COMMIT();

        const uint32_t* As = smem + buf * STAGE_FLOATS;
        const uint32_t* Bs = As + A_FLOATS;

#pragma unroll
        for (int j = 0; j < 4; j++) {
            const int colX = (8 * j + tig) ^ (g << 2);
            const int colY = colX ^ 4;
            uint32_t af[2][4], bf[8][2];
#pragma unroll
            for (int t = 0; t < 2; t++) {
                const int r0 = wm * 32 + t * 16 + g;
                af[t][0] = As[r0 * 32 + colX];
                af[t][1] = As[(r0 + 8) * 32 + colX];
                af[t][2] = As[r0 * 32 + colY];
                af[t][3] = As[(r0 + 8) * 32 + colY];
            }
#pragma unroll
            for (int u = 0; u < 8; u++) {
                const int n0 = wn * 64 + u * 8 + g;
                bf[u][0] = Bs[n0 * 32 + colX];
                bf[u][1] = Bs[n0 * 32 + colY];
            }
#pragma unroll
            for (int t = 0; t < 2; t++)
#pragma unroll
                for (int u = 0; u < 8; u++)
                    mma8(&c[(t * 8 + u) * 4], af[t], bf[u]);
        }
        __syncthreads();
    }

    // Epilogue. Round to tf32 when the result feeds another GEMM.
    constexpr bool ROUND = (EPI != EPI_RELU_SPLIT);
    const float scale = (EPI == EPI_SCALE) ? g_scale : 0.0f;
#pragma unroll
    for (int t = 0; t < 2; t++) {
        const int row0 = rowBase + wm * 32 + t * 16 + g;
#pragma unroll
        for (int u = 0; u < 8; u++) {
            const int col = colBase + wn * 64 + u * 8 + 2 * tig;
            float v0 = c[(t * 8 + u) * 4 + 0];
            float v1 = c[(t * 8 + u) * 4 + 1];
            float v2 = c[(t * 8 + u) * 4 + 2];
            float v3 = c[(t * 8 + u) * 4 + 3];
            if (EPI == EPI_SCALE) {
                v0 *= scale; v1 *= scale; v2 *= scale; v3 *= scale;
            } else {
                const float b0 = bias[col], b1 = bias[col + 1];
                v0 += b0; v1 += b1; v2 += b0; v3 += b1;
                if (EPI == EPI_RELU || EPI == EPI_RELU_SPLIT) {
                    v0 = fmaxf(v0, 0.0f); v1 = fmaxf(v1, 0.0f);
                    v2 = fmaxf(v2, 0.0f); v3 = fmaxf(v3, 0.0f);
                } else {
                    v0 = fast_tanh(v0); v1 = fast_tanh(v1);
                    v2 = fast_tanh(v2); v3 = fast_tanh(v3);
                }
            }
            if (ROUND) {
                v0 = __uint_as_float(f2tf32(v0));
                v1 = __uint_as_float(f2tf32(v1));
                v2 = __uint_as_float(f2tf32(v2));
                v3 = __uint_as_float(f2tf32(v3));
            }
            if (EPI != EPI_RELU_SPLIT) {
                *(float2*)&C0[(size_t)row0 * NC + col]       = make_float2(v0, v1);
                *(float2*)&C0[(size_t)(row0 + 8) * NC + col] = make_float2(v2, v3);
            } else {
                if (col < splitN) {
                    *(float2*)&C0[(size_t)row0 * splitN + col]       = make_float2(v0, v1);
                    *(float2*)&C0[(size_t)(row0 + 8) * splitN + col] = make_float2(v2, v3);
                } else {
                    const int c2 = col - splitN, w2 = NC - splitN;
                    *(float2*)&C1[(size_t)row0 * w2 + c2]       = make_float2(v0, v1);
                    *(float2*)&C1[(size_t)(row0 + 8) * w2 + c2] = make_float2(v2, v3);
                }
            }
        }
    }
}

// ---------------------------------------------------------------------------
// Launch
// ---------------------------------------------------------------------------
extern "C" void kernel_launch(void* const* d_in, const int* in_sizes, int n_in,
                              void* d_out, int out_size)
{
    const float* inputs = (const float*)d_in[0];
    const float* center = (const float*)d_in[1];
    const float* mstate = (const float*)d_in[2];
    const float* W_read = (const float*)d_in[3];
    const float* W_pre  = (const float*)d_in[4];
    const float* b_pre  = (const float*)d_in[5];
    const float* Wx     = (const float*)d_in[6];
    const float* Wh     = (const float*)d_in[7];
    const float* b_rnn  = (const float*)d_in[8];
    const float* W_post = (const float*)d_in[9];
    const float* b_post = (const float*)d_in[10];

    float* out  = (float*)d_out;
    float* net  = out;
    float* o2c  = out + (size_t)B_ * OUT_;
    float* hnew = out + (size_t)B_ * (OUT_ + O2C_);

    float *WpreT, *WxT, *WhT, *WpostT, *WfT, *WreadTf, *inTf, *ctrTf, *mstTf, *rnn;
    cudaGetSymbolAddress((void**)&WpreT,   g_WpreT);
    cudaGetSymbolAddress((void**)&WxT,     g_WxT);
    cudaGetSymbolAddress((void**)&WhT,     g_WhT);
    cudaGetSymbolAddress((void**)&WpostT,  g_WpostT);
    cudaGetSymbolAddress((void**)&WfT,     g_WfT);
    cudaGetSymbolAddress((void**)&WreadTf, g_WreadTf);
    cudaGetSymbolAddress((void**)&inTf,    g_inTf);
    cudaGetSymbolAddress((void**)&ctrTf,   g_ctrTf);
    cudaGetSymbolAddress((void**)&mstTf,   g_mstTf);
    cudaGetSymbolAddress((void**)&rnn,     g_rnn);

    cudaFuncSetAttribute(tgemm<EPI_SCALE>,      cudaFuncAttributeMaxDynamicSharedMemorySize, SMEM_BYTES);
    cudaFuncSetAttribute(tgemm<EPI_RELU>,       cudaFuncAttributeMaxDynamicSharedMemorySize, SMEM_BYTES);
    cudaFuncSetAttribute(tgemm<EPI_TANH>,       cudaFuncAttributeMaxDynamicSharedMemorySize, SMEM_BYTES);
    cudaFuncSetAttribute(tgemm<EPI_RELU_SPLIT>, cudaFuncAttributeMaxDynamicSharedMemorySize, SMEM_BYTES);

    dim3 tb(32, 8);

    norm_part<<<64, 256>>>(W_read);
    norm_fin<<<1, 64>>>();

    tf32_convert<<<(B_ * IN_ / 4 + 255) / 256, 256>>>(inputs, inTf, B_ * IN_ / 4);
    tf32_convert<<<(B_ * CENTER_ / 4 + 255) / 256, 256>>>(center, ctrTf, B_ * CENTER_ / 4);
    tf32_convert<<<(B_ * RNN_ / 4 + 255) / 256, 256>>>(mstate, mstTf, B_ * RNN_ / 4);
    tf32_convert<<<(CENTER_ * CTX_ / 4 + 255) / 256, 256>>>(W_read, WreadTf, CENTER_ * CTX_ / 4);

    transpose_kernel<<<dim3(FF_ / 32, (IN_ + CTX_) / 32), tb>>>(W_pre,  WpreT,  IN_ + CTX_, FF_);
    transpose_kernel<<<dim3(RNN_ / 32, FF_ / 32),  tb>>>(Wx,     WxT,    FF_,  RNN_);
    transpose_kernel<<<dim3(RNN_ / 32, RNN_ / 32), tb>>>(Wh,     WhT,    RNN_, RNN_);
    transpose_kernel<<<dim3(TOT_ / 32, RNN_ / 32), tb>>>(W_post, WpostT, RNN_, TOT_);

    // WfT = scale * (WpreT_ctx @ W_read^T)   (M=1024, N=512, K=256)
    tgemm<EPI_SCALE><<<dim3(CENTER_ / BN, FF_ / BM), NTHREADS, SMEM_BYTES>>>(
        WpreT + IN_, IN_ + CTX_, WreadTf, CTX_, CTX_,
        nullptr, 0, nullptr, 0, 0,
        nullptr, WfT, nullptr, CENTER_, 0);

    // rnn_in = relu(inputs@Wpre[:512] + center@Wf + b_pre)  (M=8192,N=1024,K=512+512)
    tgemm<EPI_RELU><<<dim3(FF_ / BN, B_ / BM), NTHREADS, SMEM_BYTES>>>(
        inTf, IN_, WpreT, IN_ + CTX_, IN_,
        ctrTf, CENTER_, WfT, CENTER_, CENTER_,
        b_pre, rnn, nullptr, FF_, 0);

    // h_new = tanh(rnn@Wx + mstate@Wh + b_rnn)  (M=8192,N=1024,K=1024+1024)
    tgemm<EPI_TANH><<<dim3(RNN_ / BN, B_ / BM), NTHREADS, SMEM_BYTES>>>(
        rnn, FF_, WxT, FF_, FF_,
        mstTf, RNN_, WhT, RNN_, RNN_,
        b_rnn, hnew, nullptr, RNN_, 0);

    // module_output = relu(h_new@W_post + b_post), split  (M=8192,N=768,K=1024)
    tgemm<EPI_RELU_SPLIT><<<dim3(TOT_ / BN, B_ / BM), NTHREADS, SMEM_BYTES>>>(
        hnew, RNN_, WpostT, RNN_, RNN_,
        nullptr, 0, nullptr, 0, 0,
        b_post, net, o2c, TOT_, OUT_);
}